// round 16
// baseline (speedup 1.0000x reference)
#include <cuda_runtime.h>
#include <cuda_fp16.h>
#include <math.h>
#include <stdint.h>

// ============================================================================
// LSTM cell, fp16 mma.sync.m16n8k16 with an asynchronous mbarrier pipeline.
//   576 threads = 16 compute warps (4 gates x 4 m-quarters, m32 x n64 each)
//                 + 2 producer warps (all cp.async issue).
//   BM=128, BK=64, 4-stage ring. NO __syncthreads in the mainloop.
//   Producer completion: cp.async.commit_group + wait_group + mbarrier.arrive
//   (no cp.async.mbarrier.arrive). No divergent __syncthreads anywhere.
// ============================================================================

#define MDIM 4096
#define NDIM 2048
#define KDIM 4096
#define BM 128
#define BN 64                 // per gate
#define BK 64                 // 128B rows
#define KT (KDIM / BK)        // 64
#define THREADS 576
#define STAGES 4

#define A_STAGE_BYTES  (BM * 128)            // 16384
#define BG_STAGE_BYTES (BN * 128)            // 8192 per gate
#define STAGE_BYTES    (A_STAGE_BYTES + 4 * BG_STAGE_BYTES)   // 49152
#define OFF_BARS       (STAGES * STAGE_BYTES)                 // 196608
#define SMEM_TOTAL     (OFF_BARS + 64)

#define SWZ(o) ((o) ^ (((o) >> 3) & 0x70))

__device__ uint4 g_Ah4[(size_t)MDIM * KDIM / 8];        // fp16 [m][k]
__device__ uint4 g_Wh4[(size_t)4 * NDIM * KDIM / 8];    // fp16 [g][n][k]

// ------------------------------ helpers ------------------------------------
__device__ __forceinline__ uint32_t smem_u32_of(const void* p) {
    uint32_t a;
    asm("{ .reg .u64 t; cvta.to.shared.u64 t, %1; cvt.u32.u64 %0, t; }" : "=r"(a) : "l"(p));
    return a;
}

#define CP_ASYNC16(dst, src) \
    asm volatile("cp.async.cg.shared.global [%0], [%1], 16;" :: "r"(dst), "l"(src) : "memory")
#define CP_COMMIT()  asm volatile("cp.async.commit_group;" ::: "memory")
#define CP_WAITG(N)  asm volatile("cp.async.wait_group %0;" :: "n"(N) : "memory")

#define MBAR_INIT(a, n) \
    asm volatile("mbarrier.init.shared.b64 [%0], %1;" :: "r"(a), "r"((uint32_t)(n)) : "memory")
#define MBAR_ARRIVE(a) \
    asm volatile("mbarrier.arrive.release.cta.shared::cta.b64 _, [%0];" :: "r"(a) : "memory")
#define MBAR_WAIT(a, ph) do {                                                     \
    uint32_t _m = (a), _p = (uint32_t)(ph), _d;                                   \
    asm volatile("{ .reg .pred p;"                                                \
        " mbarrier.try_wait.parity.acquire.cta.shared::cta.b64 p, [%1], %2;"      \
        " selp.b32 %0, 1, 0, p; }" : "=r"(_d) : "r"(_m), "r"(_p) : "memory");     \
    if (!_d) {                                                                    \
        asm volatile("{ .reg .pred P1; WL_%=:"                                    \
        " mbarrier.try_wait.parity.acquire.cta.shared::cta.b64 P1, [%0], %1, 0x989680;" \
        " @P1 bra.uni WD_%=; bra.uni WL_%=; WD_%=: }" :: "r"(_m), "r"(_p) : "memory"); \
    } } while (0)

#define LDSM_X4(d, addr) \
    asm volatile("ldmatrix.sync.aligned.m8n8.x4.shared.b16 {%0,%1,%2,%3}, [%4];" \
        : "=r"((d)[0]), "=r"((d)[1]), "=r"((d)[2]), "=r"((d)[3]) : "r"(addr))

__device__ __forceinline__ void mma16816(float c[4], const uint32_t a[4],
                                         uint32_t b0, uint32_t b1) {
    asm volatile(
        "mma.sync.aligned.m16n8k16.row.col.f32.f16.f16.f32 "
        "{%0,%1,%2,%3}, {%4,%5,%6,%7}, {%8,%9}, {%0,%1,%2,%3};\n"
        : "+f"(c[0]), "+f"(c[1]), "+f"(c[2]), "+f"(c[3])
        : "r"(a[0]), "r"(a[1]), "r"(a[2]), "r"(a[3]), "r"(b0), "r"(b1));
}

__device__ __forceinline__ float fast_tanh(float x) {
    float r; asm("tanh.approx.f32 %0, %1;" : "=f"(r) : "f"(x));
    return r;
}
__device__ __forceinline__ float fast_sigmoid(float x) {
    return 1.0f / (1.0f + __expf(-x));
}

// ------------------------------ fused pre-pass -----------------------------
__global__ void prep_all(const float* __restrict__ x, const float* __restrict__ h,
                         const float* __restrict__ Wxi, const float* __restrict__ Whi,
                         const float* __restrict__ Wxf, const float* __restrict__ Whf,
                         const float* __restrict__ Wxc, const float* __restrict__ Whc,
                         const float* __restrict__ Wxo, const float* __restrict__ Who) {
    if (blockIdx.x < 8192) {
        const size_t idx = (size_t)blockIdx.x * 256 + threadIdx.x;
        const int m = (int)(idx >> 9);
        const int k = (int)(idx & 511) * 8;
        const float* s = (k < 2048) ? x + (size_t)m * 2048 + k
                                    : h + (size_t)m * 2048 + (k - 2048);
        const float4 v0 = ((const float4*)s)[0];
        const float4 v1 = ((const float4*)s)[1];
        __half2 p0 = __floats2half2_rn(v0.x, v0.y);
        __half2 p1 = __floats2half2_rn(v0.z, v0.w);
        __half2 p2 = __floats2half2_rn(v1.x, v1.y);
        __half2 p3 = __floats2half2_rn(v1.z, v1.w);
        uint4 o;
        o.x = *(uint32_t*)&p0; o.y = *(uint32_t*)&p1;
        o.z = *(uint32_t*)&p2; o.w = *(uint32_t*)&p3;
        g_Ah4[idx] = o;
    } else {
        __shared__ float t[32][33];
        const float* Wx[4] = {Wxi, Wxf, Wxc, Wxo};
        const float* Wh[4] = {Whi, Whf, Whc, Who};
        const int b  = blockIdx.x - 8192;
        const int k0 = (b >> 6) * 32;
        const int n0 = (b & 63) * 32;
        const int tx = threadIdx.x & 31;
        const int ty = threadIdx.x >> 5;
        const int kk = k0 & 2047;
        __half* gW = (__half*)g_Wh4;
#pragma unroll
        for (int g = 0; g < 4; g++) {
            const float* src = (k0 < 2048) ? Wx[g] : Wh[g];
#pragma unroll
            for (int j = 0; j < 4; j++)
                t[ty + 8 * j][tx] = src[(size_t)(kk + ty + 8 * j) * NDIM + n0 + tx];
            __syncthreads();
#pragma unroll
            for (int j = 0; j < 4; j++)
                gW[((size_t)g * NDIM + n0 + ty + 8 * j) * KDIM + k0 + tx] =
                    __float2half_rn(t[tx][ty + 8 * j]);
            __syncthreads();
        }
    }
}

// ------------------------------ main kernel --------------------------------
// producer-side stage load: 64 threads, 3072 x 16B chunks
__device__ __forceinline__ void load_stage_p(uint32_t st, int kb, int ptid, int bm, int bn) {
    const __half* gA = (const __half*)g_Ah4;
    const __half* gW = (const __half*)g_Wh4;
#pragma unroll
    for (int i = 0; i < 48; i++) {
        const int ch = ptid + i * 64;                 // 0..3071
        if (ch < 1024) {                              // A: 128 rows x 8 chunks
            const int row = ch >> 3, c16 = ch & 7;
            const __half* src = gA + (size_t)(bm + row) * KDIM + kb + c16 * 8;
            CP_ASYNC16(st + SWZ(row * 128 + c16 * 16), src);
        } else {                                      // B: 4 gates x 64 rows x 8
            const int b = ch - 1024;
            const int gg = b >> 9, bb = b & 511;
            const int row = bb >> 3, c16 = bb & 7;
            const __half* src = gW + ((size_t)gg * NDIM + bn + row) * KDIM + kb + c16 * 8;
            CP_ASYNC16(st + A_STAGE_BYTES + gg * BG_STAGE_BYTES + SWZ(row * 128 + c16 * 16), src);
        }
    }
    CP_COMMIT();
}

__global__ __launch_bounds__(THREADS, 1)
void lstm_fp16_kernel(const float* __restrict__ cx,
                      const float* __restrict__ bi, const float* __restrict__ bf_,
                      const float* __restrict__ bc, const float* __restrict__ bo,
                      float* __restrict__ out) {
    extern __shared__ char smem[];
    const uint32_t sbase = smem_u32_of(smem);

    const int tid  = threadIdx.x;
    const int lane = tid & 31;
    const int wid  = tid >> 5;

    const int bn = blockIdx.x * BN;
    const int bm = blockIdx.y * BM;

    const uint32_t fullb = sbase + OFF_BARS;        // full[s] at +s*8
    const uint32_t freeb = sbase + OFF_BARS + 32;   // free[s] at +s*8

    if (tid == 0) {
#pragma unroll
        for (int s = 0; s < STAGES; s++) {
            MBAR_INIT(fullb + s * 8, 64);   // 64 producer threads arrive per fill
            MBAR_INIT(freeb + s * 8, 16);   // 16 compute warps arrive per use
        }
    }
    __syncthreads();

    // local fragment/acc state for compute warps (declared at top scope so the
    // eps stash after the common barrier can see it)
    float acc[2][8][4];
#pragma unroll
    for (int t = 0; t < 2; t++)
#pragma unroll
        for (int j = 0; j < 8; j++)
#pragma unroll
            for (int q = 0; q < 4; q++) acc[t][j][q] = 0.0f;

    if (wid >= 16) {
        // ---------------- producer warps ----------------
        const int ptid = tid - 512;
        for (int kt = 0; kt < KT; kt++) {
            const int s = kt & 3;
            if (kt >= STAGES) MBAR_WAIT(freeb + s * 8, ((kt - STAGES) >> 2) & 1);
            load_stage_p(sbase + s * STAGE_BYTES, kt * BK, ptid, bm, bn);
            if (kt >= 3) {                      // fill kt-3 is now complete
                CP_WAITG(3);
                MBAR_ARRIVE(fullb + ((kt - 3) & 3) * 8);
            }
        }
        // drain tail: stages KT-3, KT-2, KT-1
        CP_WAITG(2); MBAR_ARRIVE(fullb + ((KT - 3) & 3) * 8);
        CP_WAITG(1); MBAR_ARRIVE(fullb + ((KT - 2) & 3) * 8);
        CP_WAITG(0); MBAR_ARRIVE(fullb + ((KT - 1) & 3) * 8);
    } else {
        // ---------------- compute warps ----------------
        const int g  = wid & 3;    // gate
        const int mq = wid >> 2;   // m-quarter

        const int j8    = lane & 7;
        const int mm    = lane >> 3;
        const int mlo   = (mm & 1) * 8;
        const int khalf = (mm >> 1) * 16;
        const int S     = j8 << 4;
        const int rowA  = mq * 32 + mlo + j8;
        const int rowB  = mlo + j8;

        for (int kt = 0; kt < KT; kt++) {
            const int s = kt & 3;
            MBAR_WAIT(fullb + s * 8, (kt >> 2) & 1);

            const uint32_t stA = sbase + s * STAGE_BYTES;
            const uint32_t stB = stA + A_STAGE_BYTES + g * BG_STAGE_BYTES;

#pragma unroll
            for (int ks = 0; ks < 4; ks++) {
                const int KX = (ks * 32 + khalf) ^ S;
                uint32_t a[2][4], b[4][4];
                LDSM_X4(a[0], stA + rowA * 128 + KX);
                LDSM_X4(a[1], stA + (rowA + 16) * 128 + KX);
#pragma unroll
                for (int p = 0; p < 4; p++)
                    LDSM_X4(b[p], stB + (rowB + p * 16) * 128 + KX);
#pragma unroll
                for (int t = 0; t < 2; t++)
#pragma unroll
                    for (int j = 0; j < 8; j++) {
                        const int p = j >> 1, o = j & 1;
                        mma16816(acc[t][j], a[t], b[p][o], b[p][o + 2]);
                    }
            }
            __syncwarp();
            if (lane == 0) MBAR_ARRIVE(freeb + s * 8);
        }
    }

    // single COMMON barrier: all 18 warps arrive at this one statement
    __syncthreads();

    // compute warps stash accumulators into eps (stage smem is dead now)
    float* eps = (float*)smem;                 // [4][128][64] = 128 KB
    if (wid < 16) {
        const int g  = wid & 3;
        const int mq = wid >> 2;
        const int r = lane >> 2;
        const int c = lane & 3;
#pragma unroll
        for (int t = 0; t < 2; t++) {
#pragma unroll
            for (int j = 0; j < 8; j++) {
                const int row0 = mq * 32 + t * 16 + r;
                const int col0 = j * 8 + c * 2;
                eps[(g * 128 + row0) * 64 + col0]         = acc[t][j][0];
                eps[(g * 128 + row0) * 64 + col0 + 1]     = acc[t][j][1];
                eps[(g * 128 + row0 + 8) * 64 + col0]     = acc[t][j][2];
                eps[(g * 128 + row0 + 8) * 64 + col0 + 1] = acc[t][j][3];
            }
        }
    }
    __syncthreads();

    // ---- elementwise epilogue: all 576 threads ----
    const size_t outCY = (size_t)MDIM * NDIM;
    for (int idx4 = tid; idx4 < 128 * 16; idx4 += THREADS) {
        const int ml  = idx4 >> 4;
        const int nl4 = (idx4 & 15) * 4;
        const int gm  = bm + ml;
        const int gn  = bn + nl4;

        const float4 vi4 = *(const float4*)(eps + (0 * 128 + ml) * 64 + nl4);
        const float4 vf4 = *(const float4*)(eps + (1 * 128 + ml) * 64 + nl4);
        const float4 vc4 = *(const float4*)(eps + (2 * 128 + ml) * 64 + nl4);
        const float4 vo4 = *(const float4*)(eps + (3 * 128 + ml) * 64 + nl4);
        const float4 cp4 = *(const float4*)(cx + (size_t)gm * NDIM + gn);
        const float4 bi4 = *(const float4*)(bi + gn);
        const float4 bf4 = *(const float4*)(bf_ + gn);
        const float4 bc4 = *(const float4*)(bc + gn);
        const float4 bo4 = *(const float4*)(bo + gn);

        float hy[4], cyv[4];
        const float* vi = &vi4.x; const float* vf = &vf4.x;
        const float* vc = &vc4.x; const float* vo = &vo4.x;
        const float* cp = &cp4.x;
        const float* pbi = &bi4.x; const float* pbf = &bf4.x;
        const float* pbc = &bc4.x; const float* pbo = &bo4.x;
#pragma unroll
        for (int q = 0; q < 4; q++) {
            const float zi = vi[q] + pbi[q];
            const float zf = vf[q] + pbf[q];
            const float zc = vc[q] + pbc[q];
            const float zo = vo[q] + pbo[q];
            const float ig = fast_sigmoid(zi);
            const float fg = fast_sigmoid(zf);
            const float og = fast_sigmoid(zo);
            const float ct = fast_tanh(zc);
            cyv[q] = fg * cp[q] + ig * ct;
            hy[q]  = og * fast_tanh(cyv[q]);
        }
        *(float4*)(out + (size_t)gm * NDIM + gn) = make_float4(hy[0], hy[1], hy[2], hy[3]);
        *(float4*)(out + outCY + (size_t)gm * NDIM + gn) = make_float4(cyv[0], cyv[1], cyv[2], cyv[3]);
    }
}

// ------------------------------- launch ------------------------------------
extern "C" void kernel_launch(void* const* d_in, const int* in_sizes, int n_in,
                              void* d_out, int out_size) {
    (void)in_sizes; (void)n_in; (void)out_size;
    cudaFuncSetAttribute(lstm_fp16_kernel,
                         cudaFuncAttributeMaxDynamicSharedMemorySize, SMEM_TOTAL);

    prep_all<<<16384, 256>>>(
        (const float*)d_in[0],  (const float*)d_in[1],    // x, h_x
        (const float*)d_in[3],  (const float*)d_in[4],    // W_xi, W_hi
        (const float*)d_in[6],  (const float*)d_in[7],    // W_xf, W_hf
        (const float*)d_in[9],  (const float*)d_in[10],   // W_xc, W_hc
        (const float*)d_in[12], (const float*)d_in[13]);  // W_xo, W_ho

    dim3 grid(NDIM / BN, MDIM / BM);   // 32 x 32 = 1024 CTAs
    lstm_fp16_kernel<<<grid, THREADS, SMEM_TOTAL>>>(
        (const float*)d_in[2],                           // c_x
        (const float*)d_in[5],  (const float*)d_in[8],   // b_i, b_f
        (const float*)d_in[11], (const float*)d_in[14],  // b_c, b_o
        (float*)d_out);
}